// round 1
// baseline (speedup 1.0000x reference)
#include <cuda_runtime.h>
#include <math.h>

// ---------------- problem constants ----------------
#define BB   16
#define TT   2048
#define LL   512
#define HH   256
#define HH2  512
#define CVQd 64
#define KCBd 128
#define NLB  10   // NL * NB

// ---------------- scratch (single device global, no allocs) ----------------
// bx, bn, by : [B,H,T]  = 8,388,608 floats each
// bm         : [B,2H,T] = 16,777,216
// seg        : [B,H,L+1]= 2,101,248
// cnt        : [B,L+1]  = 8,208
// bz, bq     : [B,CVQ,L]= 524,288 each
// loss       : 1  (+pad)
#define SZ_BHT  ((size_t)BB*HH*TT)
#define SZ_BMT  ((size_t)BB*HH2*TT)
#define SZ_SEG  ((size_t)BB*HH*(LL+1))
#define SZ_CNT  ((size_t)BB*(LL+1))
#define SZ_BZL  ((size_t)BB*CVQd*LL)
__device__ float g_scratch[3*SZ_BHT + SZ_BMT + SZ_SEG + SZ_CNT + 2*SZ_BZL + 64];

// ---------------- LayerNorm over channel dim of [B,C,T] ----------------
__global__ void ln_kernel(const float* __restrict__ in, float* __restrict__ out,
                          const float* __restrict__ gma, const float* __restrict__ bta,
                          const float* __restrict__ mask, int Tdim)
{
    int idx = blockIdx.x * blockDim.x + threadIdx.x;    // over B*Tdim
    if (idx >= BB * Tdim) return;
    int b = idx / Tdim, t = idx - b * Tdim;
    const float* p = in + (size_t)b * HH * Tdim + t;
    float s = 0.f, s2 = 0.f;
    #pragma unroll 8
    for (int c = 0; c < HH; c++) { float v = p[(size_t)c * Tdim]; s += v; s2 += v * v; }
    float mean = s * (1.f / HH);
    float var  = s2 * (1.f / HH) - mean * mean;
    float r = rsqrtf(var + 1e-5f);
    float mk = mask ? mask[b * Tdim + t] : 1.f;
    float* o = out + (size_t)b * HH * Tdim + t;
    #pragma unroll 8
    for (int c = 0; c < HH; c++) {
        float v = p[(size_t)c * Tdim];
        o[(size_t)c * Tdim] = ((v - mean) * r * gma[c] + bta[c]) * mk;
    }
}

// ---------------- causal conv k=3 (Cin -> Cout), optional scale/gelu/mask ----------------
// 64(co) x 64(t) tile, K-chunk 32, 256 threads, 4x4 per thread
__global__ void cconv_kernel(const float* __restrict__ in, const float* __restrict__ w,
                             const float* __restrict__ bias, float* __restrict__ out,
                             const float* __restrict__ mask,
                             int Cin, int Cout, int Tdim, float scale, int dogelu)
{
    __shared__ float ws[64][97];   // [co][ci*3+k]
    __shared__ float xs[32][68];   // [ci][t window 66]
    int b = blockIdx.z, cog = blockIdx.y * 64, tg = blockIdx.x * 64;
    int tid = threadIdx.x;
    float acc[4][4] = {};
    const float* inB = in + (size_t)b * Cin * Tdim;

    for (int kc = 0; kc < Cin; kc += 32) {
        for (int l = tid; l < 64 * 96; l += 256) {
            int co = l / 96, r = l - co * 96;
            int ci = r / 3, k = r - ci * 3;
            ws[co][r] = w[((size_t)(cog + co) * Cin + kc + ci) * 3 + k];
        }
        for (int l = tid; l < 32 * 66; l += 256) {
            int ci = l / 66, j = l - ci * 66;
            int t = tg + j - 2;
            xs[ci][j] = (t >= 0) ? inB[(size_t)(kc + ci) * Tdim + t] : 0.f;
        }
        __syncthreads();
        int tn0 = (tid & 15) * 4, cn0 = (tid >> 4) * 4;
        #pragma unroll
        for (int ci = 0; ci < 32; ci++) {
            float xv[6];
            #pragma unroll
            for (int j = 0; j < 6; j++) xv[j] = xs[ci][tn0 + j];
            #pragma unroll
            for (int i = 0; i < 4; i++) {
                #pragma unroll
                for (int k = 0; k < 3; k++) {
                    float wv = ws[cn0 + i][ci * 3 + k];
                    #pragma unroll
                    for (int j = 0; j < 4; j++) acc[i][j] += wv * xv[j + k];
                }
            }
        }
        __syncthreads();
    }
    int tn0 = (tid & 15) * 4, cn0 = (tid >> 4) * 4;
    #pragma unroll
    for (int i = 0; i < 4; i++) {
        int co = cog + cn0 + i;
        float bi = bias[co];
        #pragma unroll
        for (int j = 0; j < 4; j++) {
            int t = tg + tn0 + j;
            float v = (acc[i][j] + bi) * scale;
            if (dogelu) v = 0.5f * v * (1.f + erff(v * 0.70710678118654752f));
            if (mask) v *= mask[b * Tdim + t];
            out[((size_t)b * Cout + co) * Tdim + t] = v;
        }
    }
}

// ---------------- pointwise conv (GEMM), optional residual/mask ----------------
__global__ void pw_kernel(const float* __restrict__ in, const float* __restrict__ w,
                          const float* __restrict__ bias, float* __restrict__ out,
                          const float* __restrict__ residual, const float* __restrict__ mask,
                          int Cin, int Cout, int Tdim)
{
    __shared__ float ws[64][33];
    __shared__ float xs[32][68];
    int b = blockIdx.z, cog = blockIdx.y * 64, tg = blockIdx.x * 64;
    int tid = threadIdx.x;
    float acc[4][4] = {};
    const float* inB = in + (size_t)b * Cin * Tdim;

    for (int kc = 0; kc < Cin; kc += 32) {
        for (int l = tid; l < 64 * 32; l += 256) {
            int co = l >> 5, ci = l & 31;
            ws[co][ci] = (kc + ci < Cin) ? w[(size_t)(cog + co) * Cin + kc + ci] : 0.f;
        }
        for (int l = tid; l < 32 * 64; l += 256) {
            int ci = l >> 6, j = l & 63;
            xs[ci][j] = (kc + ci < Cin) ? inB[(size_t)(kc + ci) * Tdim + tg + j] : 0.f;
        }
        __syncthreads();
        int tn0 = (tid & 15) * 4, cn0 = (tid >> 4) * 4;
        #pragma unroll
        for (int ci = 0; ci < 32; ci++) {
            float xv0 = xs[ci][tn0], xv1 = xs[ci][tn0 + 1], xv2 = xs[ci][tn0 + 2], xv3 = xs[ci][tn0 + 3];
            #pragma unroll
            for (int i = 0; i < 4; i++) {
                float wv = ws[cn0 + i][ci];
                acc[i][0] += wv * xv0; acc[i][1] += wv * xv1;
                acc[i][2] += wv * xv2; acc[i][3] += wv * xv3;
            }
        }
        __syncthreads();
    }
    int tn0 = (tid & 15) * 4, cn0 = (tid >> 4) * 4;
    #pragma unroll
    for (int i = 0; i < 4; i++) {
        int co = cog + cn0 + i;
        float bi = bias[co];
        #pragma unroll
        for (int j = 0; j < 4; j++) {
            int t = tg + tn0 + j;
            size_t oi = ((size_t)b * Cout + co) * Tdim + t;
            float v = acc[i][j] + bi;
            if (residual) v += residual[oi];
            if (mask) v *= mask[b * Tdim + t];
            out[oi] = v;
        }
    }
}

// ---------------- group_by_segs ----------------
__global__ void seg_zero(float* seg, float* cnt)
{
    int i = blockIdx.x * blockDim.x + threadIdx.x;
    if (i < (int)SZ_SEG) seg[i] = 0.f;
    if (i < (int)SZ_CNT) cnt[i] = 0.f;
}
__global__ void seg_scatter(const float* __restrict__ in, const int* __restrict__ mel2ph,
                            float* seg, float* cnt)
{
    int t = blockIdx.x, b = blockIdx.y, c = threadIdx.x;
    int ph = mel2ph[b * TT + t];
    if (ph < 1 || ph > LL) return;
    float v = in[((size_t)b * HH + c) * TT + t];
    atomicAdd(&seg[((size_t)b * HH + c) * (LL + 1) + ph], v);
    if (c == 0) atomicAdd(&cnt[b * (LL + 1) + ph], 1.f);
}
__global__ void seg_div(const float* __restrict__ seg, const float* __restrict__ cnt,
                        float* __restrict__ outg)
{
    int i = blockIdx.x * blockDim.x + threadIdx.x;   // over B*H*L
    if (i >= BB * HH * LL) return;
    int l = i % LL; int bc = i / LL; int c = bc % HH; int b = bc / HH;
    float s = seg[((size_t)b * HH + c) * (LL + 1) + l + 1];
    float n = fmaxf(cnt[b * (LL + 1) + l + 1], 1.f);
    outg[i] = s / n;
}

// ---------------- VQ ----------------
__global__ void loss_init(float* loss) { if (threadIdx.x == 0) *loss = 0.f; }

__global__ void vq_kernel(const float* __restrict__ z, const float* __restrict__ cb,
                          float* __restrict__ q, float* __restrict__ outIdx, float* loss)
{
    __shared__ float zsh[64];
    __shared__ float dsh[128];
    __shared__ int   ish[128];
    int l = blockIdx.x, b = blockIdx.y, tid = threadIdx.x;
    if (tid < 64) zsh[tid] = z[((size_t)b * CVQd + tid) * LL + l];
    __syncthreads();
    float x2 = 0.f, dot = 0.f, c2 = 0.f;
    #pragma unroll 8
    for (int c = 0; c < 64; c++) {
        float zv = zsh[c]; float cv = cb[tid * 64 + c];
        x2 += zv * zv; dot += zv * cv; c2 += cv * cv;
    }
    dsh[tid] = x2 - 2.f * dot + c2;
    ish[tid] = tid;
    __syncthreads();
    for (int s = 64; s > 0; s >>= 1) {
        if (tid < s) {
            float d2 = dsh[tid + s]; int i2 = ish[tid + s];
            if (d2 < dsh[tid] || (d2 == dsh[tid] && i2 < ish[tid])) { dsh[tid] = d2; ish[tid] = i2; }
        }
        __syncthreads();
    }
    int best = ish[0];
    __syncthreads();
    float part = 0.f;
    if (tid < 64) {
        float qv = cb[best * 64 + tid];
        q[((size_t)b * CVQd + tid) * LL + l] = qv;
        float dd = zsh[tid] - qv;
        part = dd * dd;
    }
    dsh[tid] = part;
    __syncthreads();
    for (int s = 64; s > 0; s >>= 1) { if (tid < s) dsh[tid] += dsh[tid + s]; __syncthreads(); }
    if (tid == 0) {
        atomicAdd(loss, dsh[0]);
        outIdx[b * LL + l] = (float)best;
    }
}

__global__ void loss_fin(const float* loss, float* out)
{
    out[0] = loss[0] * 0.25f / (float)(BB * LL * CVQd);
}

// ---------------- launch ----------------
extern "C" void kernel_launch(void* const* d_in, const int* in_sizes, int n_in,
                              void* d_out, int out_size)
{
    float* scratch = nullptr;
    cudaGetSymbolAddress((void**)&scratch, g_scratch);
    float* bx  = scratch;
    float* bn  = bx + SZ_BHT;
    float* by  = bn + SZ_BHT;
    float* bm  = by + SZ_BHT;
    float* seg = bm + SZ_BMT;
    float* cnt = seg + SZ_SEG;
    float* bz  = cnt + SZ_CNT;
    float* bq  = bz + SZ_BZL;
    float* loss = bq + SZ_BZL;

    const float* x        = (const float*)d_in[0];
    const float* in_mask  = (const float*)d_in[1];
    const int*   mel2ph   = (const int*)  d_in[2];
    const float* ph_mask  = (const float*)d_in[3];
    const float* conv_in_w = (const float*)d_in[4];
    const float* conv_in_b = (const float*)d_in[5];
    const float* enc_ln_g = (const float*)d_in[6];
    const float* enc_ln_b = (const float*)d_in[7];
    const float* enc_w1   = (const float*)d_in[8];
    const float* enc_b1   = (const float*)d_in[9];
    const float* enc_w2   = (const float*)d_in[10];
    const float* enc_b2   = (const float*)d_in[11];
    const float* enc_last_g = (const float*)d_in[12];
    const float* enc_last_b = (const float*)d_in[13];
    const float* enc_post_w = (const float*)d_in[14];
    const float* enc_post_b = (const float*)d_in[15];
    const float* pn_ln_g = (const float*)d_in[16];
    const float* pn_ln_b = (const float*)d_in[17];
    const float* pn_w1   = (const float*)d_in[18];
    const float* pn_b1   = (const float*)d_in[19];
    const float* pn_w2   = (const float*)d_in[20];
    const float* pn_b2   = (const float*)d_in[21];
    const float* pn_last_g = (const float*)d_in[22];
    const float* pn_last_b = (const float*)d_in[23];
    const float* pn_post_w = (const float*)d_in[24];
    const float* pn_post_b = (const float*)d_in[25];
    const float* proj_in_w  = (const float*)d_in[26];
    const float* proj_in_b  = (const float*)d_in[27];
    const float* proj_out_w = (const float*)d_in[28];
    const float* proj_out_b = (const float*)d_in[29];
    const float* codebook   = (const float*)d_in[30];

    float* out = (float*)d_out;
    const float scale = 0.57735026918962576f;   // 3^-0.5
    dim3 blk(256);

    // ---- encoder (T = TT) ----
    pw_kernel<<<dim3(TT / 64, HH / 64, BB), blk>>>(x, conv_in_w, conv_in_b, bx,
                                                   nullptr, in_mask, 80, HH, TT);
    for (int i = 0; i < NLB; i++) {
        ln_kernel<<<(BB * TT + 255) / 256, 256>>>(bx, bn, enc_ln_g + i * HH, enc_ln_b + i * HH,
                                                  nullptr, TT);
        cconv_kernel<<<dim3(TT / 64, HH2 / 64, BB), blk>>>(bn, enc_w1 + (size_t)i * HH2 * HH * 3,
                                                           enc_b1 + i * HH2, bm, nullptr,
                                                           HH, HH2, TT, scale, 1);
        pw_kernel<<<dim3(TT / 64, HH / 64, BB), blk>>>(bm, enc_w2 + (size_t)i * HH * HH2,
                                                       enc_b2 + i * HH, bx, bx, in_mask,
                                                       HH2, HH, TT);
    }
    ln_kernel<<<(BB * TT + 255) / 256, 256>>>(bx, bn, enc_last_g, enc_last_b, in_mask, TT);
    cconv_kernel<<<dim3(TT / 64, HH / 64, BB), blk>>>(bn, enc_post_w, enc_post_b, by, in_mask,
                                                      HH, HH, TT, 1.f, 0);

    // ---- group by segments -> [B,H,L] into bx ----
    seg_zero<<<((int)SZ_SEG + 255) / 256, 256>>>(seg, cnt);
    seg_scatter<<<dim3(TT, BB), HH>>>(by, mel2ph, seg, cnt);
    seg_div<<<(BB * HH * LL + 255) / 256, 256>>>(seg, cnt, bx);

    // ---- postnet (T = LL) ----
    for (int i = 0; i < NLB; i++) {
        ln_kernel<<<(BB * LL + 255) / 256, 256>>>(bx, bn, pn_ln_g + i * HH, pn_ln_b + i * HH,
                                                  nullptr, LL);
        cconv_kernel<<<dim3(LL / 64, HH2 / 64, BB), blk>>>(bn, pn_w1 + (size_t)i * HH2 * HH * 3,
                                                           pn_b1 + i * HH2, bm, nullptr,
                                                           HH, HH2, LL, scale, 1);
        pw_kernel<<<dim3(LL / 64, HH / 64, BB), blk>>>(bm, pn_w2 + (size_t)i * HH * HH2,
                                                       pn_b2 + i * HH, bx, bx, ph_mask,
                                                       HH2, HH, LL);
    }
    ln_kernel<<<(BB * LL + 255) / 256, 256>>>(bx, bn, pn_last_g, pn_last_b, ph_mask, LL);
    cconv_kernel<<<dim3(LL / 64, HH / 64, BB), blk>>>(bn, pn_post_w, pn_post_b, by, ph_mask,
                                                      HH, HH, LL, 1.f, 0);

    // ---- proj_in -> VQ -> proj_out ----
    pw_kernel<<<dim3(LL / 64, CVQd / 64, BB), blk>>>(by, proj_in_w, proj_in_b, bz,
                                                     nullptr, nullptr, HH, CVQd, LL);
    loss_init<<<1, 32>>>(loss);
    vq_kernel<<<dim3(LL, BB), 128>>>(bz, codebook, bq, out + (size_t)BB * HH * LL + 1, loss);
    pw_kernel<<<dim3(LL / 64, HH / 64, BB), blk>>>(bq, proj_out_w, proj_out_b, out,
                                                   nullptr, nullptr, CVQd, HH, LL);
    loss_fin<<<1, 1>>>(loss, out + (size_t)BB * HH * LL);
}

// round 2
// speedup vs baseline: 1.2223x; 1.2223x over previous
#include <cuda_runtime.h>
#include <math.h>
#include <stdint.h>

// ---------------- problem constants ----------------
#define BB   16
#define TT   2048
#define LL   512
#define HH   256
#define HH2  512
#define CVQd 64
#define KCBd 128
#define NLB  10   // NL * NB

// ---------------- scratch ----------------
#define SZ_BHT  ((size_t)BB*HH*TT)
#define SZ_BMT  ((size_t)BB*HH2*TT)
#define SZ_SEG  ((size_t)BB*HH*(LL+1))
#define SZ_CNT  ((size_t)BB*(LL+1))
#define SZ_BZL  ((size_t)BB*CVQd*LL)
__device__ float g_scratch[3*SZ_BHT + SZ_BMT + SZ_SEG + SZ_CNT + 2*SZ_BZL + 64];

// ---------------- helpers ----------------
__device__ __forceinline__ float tf32_rna(float x) {
    uint32_t u;
    asm("cvt.rna.tf32.f32 %0, %1;" : "=r"(u) : "f"(x));
    return __uint_as_float(u);
}

#define MMA_TF32(C, A, B)                                                        \
    asm volatile("mma.sync.aligned.m16n8k8.row.col.f32.tf32.tf32.f32 "           \
        "{%0,%1,%2,%3}, {%4,%5,%6,%7}, {%8,%9}, {%0,%1,%2,%3};"                  \
        : "+f"((C)[0]), "+f"((C)[1]), "+f"((C)[2]), "+f"((C)[3])                  \
        : "r"((A)[0]), "r"((A)[1]), "r"((A)[2]), "r"((A)[3]),                     \
          "r"((B)[0]), "r"((B)[1]))

// ---------------- LayerNorm over channel dim of [B,C,T] ----------------
__global__ void ln_kernel(const float* __restrict__ in, float* __restrict__ out,
                          const float* __restrict__ gma, const float* __restrict__ bta,
                          const float* __restrict__ mask, int Tdim)
{
    int idx = blockIdx.x * blockDim.x + threadIdx.x;
    if (idx >= BB * Tdim) return;
    int b = idx / Tdim, t = idx - b * Tdim;
    const float* p = in + (size_t)b * HH * Tdim + t;
    float s = 0.f, s2 = 0.f;
    #pragma unroll 8
    for (int c = 0; c < HH; c++) { float v = p[(size_t)c * Tdim]; s += v; s2 += v * v; }
    float mean = s * (1.f / HH);
    float var  = s2 * (1.f / HH) - mean * mean;
    float r = rsqrtf(var + 1e-5f);
    float mk = mask ? mask[b * Tdim + t] : 1.f;
    float* o = out + (size_t)b * HH * Tdim + t;
    #pragma unroll 8
    for (int c = 0; c < HH; c++) {
        float v = p[(size_t)c * Tdim];
        o[(size_t)c * Tdim] = ((v - mean) * r * gma[c] + bta[c]) * mk;
    }
}

// ---------------- 3xTF32 tensor-core conv GEMM ----------------
// out[b, co, t] = sum_{ci,tap} w[co, ci, tap] * in[b, ci, t + tap - (KS-1)]
// BM=64 (Cout) x BN=128 (T) tile, BK=16, 256 threads, 8 warps (2M x 4N).
template<int KS>
__global__ void __launch_bounds__(256)
mma_conv(const float* __restrict__ in, const float* __restrict__ w,
         const float* __restrict__ bias, float* out,
         const float* residual, const float* __restrict__ mask,
         int Cin, int Cout, int Tdim, float scale, int dogelu)
{
    __shared__ float Ah[64 * 17], Al[64 * 17];    // [m][k], stride 17
    __shared__ float Bh[16 * 136], Bl[16 * 136];  // [k][n], stride 136

    const int b   = blockIdx.z;
    const int cog = blockIdx.y * 64;
    const int tg  = blockIdx.x * 128;
    const int tid = threadIdx.x;
    const int wid = tid >> 5, lane = tid & 31;
    const int wm = wid >> 2, wn = wid & 3;       // 2M x 4N warps
    const int g = lane >> 2, th = lane & 3;

    const int KT = Cin * KS;
    const float* inB = in + (size_t)b * Cin * Tdim;

    float c[2][4][4];
    #pragma unroll
    for (int i = 0; i < 2; i++)
        #pragma unroll
        for (int j = 0; j < 4; j++)
            #pragma unroll
            for (int k = 0; k < 4; k++) c[i][j][k] = 0.f;

    for (int kc = 0; kc < KT; kc += 16) {
        const int tap = kc / Cin;
        const int ci0 = kc - tap * Cin;
        const int tshift = tap - (KS - 1);

        // ---- load A tile: 64 x 16 ----
        #pragma unroll
        for (int i = 0; i < 4; i++) {
            int idx = i * 256 + tid;
            int k = idx & 15, m = idx >> 4;
            float v = w[(size_t)(cog + m) * KT + (ci0 + k) * KS + tap];
            float h = tf32_rna(v);
            Ah[m * 17 + k] = h;
            Al[m * 17 + k] = tf32_rna(v - h);
        }
        // ---- load B tile: 16 x 128 (with causal shift) ----
        #pragma unroll
        for (int i = 0; i < 8; i++) {
            int idx = i * 256 + tid;
            int row = idx >> 7, col = idx & 127;
            int t = tg + col + tshift;
            float v = (t >= 0) ? inB[(size_t)(ci0 + row) * Tdim + t] : 0.f;
            float h = tf32_rna(v);
            Bh[row * 136 + col] = h;
            Bl[row * 136 + col] = tf32_rna(v - h);
        }
        __syncthreads();

        #pragma unroll
        for (int ks = 0; ks < 2; ks++) {
            const int k0 = ks * 8;
            uint32_t ah[2][4], al[2][4], bh[4][2], bl[4][2];
            #pragma unroll
            for (int mf = 0; mf < 2; mf++) {
                int m = wm * 32 + mf * 16 + g;
                ah[mf][0] = __float_as_uint(Ah[(m)     * 17 + k0 + th]);
                ah[mf][1] = __float_as_uint(Ah[(m + 8) * 17 + k0 + th]);
                ah[mf][2] = __float_as_uint(Ah[(m)     * 17 + k0 + th + 4]);
                ah[mf][3] = __float_as_uint(Ah[(m + 8) * 17 + k0 + th + 4]);
                al[mf][0] = __float_as_uint(Al[(m)     * 17 + k0 + th]);
                al[mf][1] = __float_as_uint(Al[(m + 8) * 17 + k0 + th]);
                al[mf][2] = __float_as_uint(Al[(m)     * 17 + k0 + th + 4]);
                al[mf][3] = __float_as_uint(Al[(m + 8) * 17 + k0 + th + 4]);
            }
            #pragma unroll
            for (int nf = 0; nf < 4; nf++) {
                int n = wn * 32 + nf * 8 + g;
                bh[nf][0] = __float_as_uint(Bh[(k0 + th)     * 136 + n]);
                bh[nf][1] = __float_as_uint(Bh[(k0 + th + 4) * 136 + n]);
                bl[nf][0] = __float_as_uint(Bl[(k0 + th)     * 136 + n]);
                bl[nf][1] = __float_as_uint(Bl[(k0 + th + 4) * 136 + n]);
            }
            #pragma unroll
            for (int mf = 0; mf < 2; mf++)
                #pragma unroll
                for (int nf = 0; nf < 4; nf++) {
                    MMA_TF32(c[mf][nf], ah[mf], bh[nf]);
                    MMA_TF32(c[mf][nf], ah[mf], bl[nf]);
                    MMA_TF32(c[mf][nf], al[mf], bh[nf]);
                }
        }
        __syncthreads();
    }

    // ---- epilogue ----
    #pragma unroll
    for (int mf = 0; mf < 2; mf++) {
        int m0 = cog + wm * 32 + mf * 16 + g;
        float bi0 = bias[m0], bi1 = bias[m0 + 8];
        #pragma unroll
        for (int nf = 0; nf < 4; nf++) {
            int t0 = tg + wn * 32 + nf * 8 + 2 * th;
            #pragma unroll
            for (int half = 0; half < 2; half++) {
                int m = half ? m0 + 8 : m0;
                float bi = half ? bi1 : bi0;
                float v0 = (c[mf][nf][half * 2 + 0] + bi) * scale;
                float v1 = (c[mf][nf][half * 2 + 1] + bi) * scale;
                if (dogelu) {
                    v0 = 0.5f * v0 * (1.f + erff(v0 * 0.70710678118654752f));
                    v1 = 0.5f * v1 * (1.f + erff(v1 * 0.70710678118654752f));
                }
                size_t oi = ((size_t)b * Cout + m) * Tdim + t0;
                if (residual) { v0 += residual[oi]; v1 += residual[oi + 1]; }
                if (mask) {
                    float mk0 = mask[b * Tdim + t0], mk1 = mask[b * Tdim + t0 + 1];
                    v0 *= mk0; v1 *= mk1;
                }
                out[oi] = v0; out[oi + 1] = v1;
            }
        }
    }
}

// ---------------- group_by_segs ----------------
__global__ void seg_zero(float* seg, float* cnt)
{
    int i = blockIdx.x * blockDim.x + threadIdx.x;
    if (i < (int)SZ_SEG) seg[i] = 0.f;
    if (i < (int)SZ_CNT) cnt[i] = 0.f;
}
__global__ void seg_scatter(const float* __restrict__ in, const int* __restrict__ mel2ph,
                            float* seg, float* cnt)
{
    int t = blockIdx.x, b = blockIdx.y, c = threadIdx.x;
    int ph = mel2ph[b * TT + t];
    if (ph < 1 || ph > LL) return;
    float v = in[((size_t)b * HH + c) * TT + t];
    atomicAdd(&seg[((size_t)b * HH + c) * (LL + 1) + ph], v);
    if (c == 0) atomicAdd(&cnt[b * (LL + 1) + ph], 1.f);
}
__global__ void seg_div(const float* __restrict__ seg, const float* __restrict__ cnt,
                        float* __restrict__ outg)
{
    int i = blockIdx.x * blockDim.x + threadIdx.x;
    if (i >= BB * HH * LL) return;
    int l = i % LL; int bc = i / LL; int c = bc % HH; int b = bc / HH;
    float s = seg[((size_t)b * HH + c) * (LL + 1) + l + 1];
    float n = fmaxf(cnt[b * (LL + 1) + l + 1], 1.f);
    outg[i] = s / n;
}

// ---------------- VQ ----------------
__global__ void loss_init(float* loss) { if (threadIdx.x == 0) *loss = 0.f; }

__global__ void vq_kernel(const float* __restrict__ z, const float* __restrict__ cb,
                          float* __restrict__ q, float* __restrict__ outIdx, float* loss)
{
    __shared__ float zsh[64];
    __shared__ float dsh[128];
    __shared__ int   ish[128];
    int l = blockIdx.x, b = blockIdx.y, tid = threadIdx.x;
    if (tid < 64) zsh[tid] = z[((size_t)b * CVQd + tid) * LL + l];
    __syncthreads();
    float x2 = 0.f, dot = 0.f, c2 = 0.f;
    #pragma unroll 8
    for (int c = 0; c < 64; c++) {
        float zv = zsh[c]; float cv = cb[tid * 64 + c];
        x2 += zv * zv; dot += zv * cv; c2 += cv * cv;
    }
    dsh[tid] = x2 - 2.f * dot + c2;
    ish[tid] = tid;
    __syncthreads();
    for (int s = 64; s > 0; s >>= 1) {
        if (tid < s) {
            float d2 = dsh[tid + s]; int i2 = ish[tid + s];
            if (d2 < dsh[tid] || (d2 == dsh[tid] && i2 < ish[tid])) { dsh[tid] = d2; ish[tid] = i2; }
        }
        __syncthreads();
    }
    int best = ish[0];
    __syncthreads();
    float part = 0.f;
    if (tid < 64) {
        float qv = cb[best * 64 + tid];
        q[((size_t)b * CVQd + tid) * LL + l] = qv;
        float dd = zsh[tid] - qv;
        part = dd * dd;
    }
    dsh[tid] = part;
    __syncthreads();
    for (int s = 64; s > 0; s >>= 1) { if (tid < s) dsh[tid] += dsh[tid + s]; __syncthreads(); }
    if (tid == 0) {
        atomicAdd(loss, dsh[0]);
        outIdx[b * LL + l] = (float)best;
    }
}

__global__ void loss_fin(const float* loss, float* out)
{
    out[0] = loss[0] * 0.25f / (float)(BB * LL * CVQd);
}

// ---------------- launch ----------------
extern "C" void kernel_launch(void* const* d_in, const int* in_sizes, int n_in,
                              void* d_out, int out_size)
{
    float* scratch = nullptr;
    cudaGetSymbolAddress((void**)&scratch, g_scratch);
    float* bx  = scratch;
    float* bn  = bx + SZ_BHT;
    float* by  = bn + SZ_BHT;
    float* bm  = by + SZ_BHT;
    float* seg = bm + SZ_BMT;
    float* cnt = seg + SZ_SEG;
    float* bz  = cnt + SZ_CNT;
    float* bq  = bz + SZ_BZL;
    float* loss = bq + SZ_BZL;

    const float* x        = (const float*)d_in[0];
    const float* in_mask  = (const float*)d_in[1];
    const int*   mel2ph   = (const int*)  d_in[2];
    const float* ph_mask  = (const float*)d_in[3];
    const float* conv_in_w = (const float*)d_in[4];
    const float* conv_in_b = (const float*)d_in[5];
    const float* enc_ln_g = (const float*)d_in[6];
    const float* enc_ln_b = (const float*)d_in[7];
    const float* enc_w1   = (const float*)d_in[8];
    const float* enc_b1   = (const float*)d_in[9];
    const float* enc_w2   = (const float*)d_in[10];
    const float* enc_b2   = (const float*)d_in[11];
    const float* enc_last_g = (const float*)d_in[12];
    const float* enc_last_b = (const float*)d_in[13];
    const float* enc_post_w = (const float*)d_in[14];
    const float* enc_post_b = (const float*)d_in[15];
    const float* pn_ln_g = (const float*)d_in[16];
    const float* pn_ln_b = (const float*)d_in[17];
    const float* pn_w1   = (const float*)d_in[18];
    const float* pn_b1   = (const float*)d_in[19];
    const float* pn_w2   = (const float*)d_in[20];
    const float* pn_b2   = (const float*)d_in[21];
    const float* pn_last_g = (const float*)d_in[22];
    const float* pn_last_b = (const float*)d_in[23];
    const float* pn_post_w = (const float*)d_in[24];
    const float* pn_post_b = (const float*)d_in[25];
    const float* proj_in_w  = (const float*)d_in[26];
    const float* proj_in_b  = (const float*)d_in[27];
    const float* proj_out_w = (const float*)d_in[28];
    const float* proj_out_b = (const float*)d_in[29];
    const float* codebook   = (const float*)d_in[30];

    float* out = (float*)d_out;
    const float scale = 0.57735026918962576f;   // 3^-0.5
    dim3 blk(256);

    // ---- encoder (T = TT) ----
    mma_conv<1><<<dim3(TT / 128, HH / 64, BB), blk>>>(x, conv_in_w, conv_in_b, bx,
                                                      nullptr, in_mask, 80, HH, TT, 1.f, 0);
    for (int i = 0; i < NLB; i++) {
        ln_kernel<<<(BB * TT + 255) / 256, 256>>>(bx, bn, enc_ln_g + i * HH, enc_ln_b + i * HH,
                                                  nullptr, TT);
        mma_conv<3><<<dim3(TT / 128, HH2 / 64, BB), blk>>>(bn, enc_w1 + (size_t)i * HH2 * HH * 3,
                                                           enc_b1 + i * HH2, bm, nullptr, nullptr,
                                                           HH, HH2, TT, scale, 1);
        mma_conv<1><<<dim3(TT / 128, HH / 64, BB), blk>>>(bm, enc_w2 + (size_t)i * HH * HH2,
                                                          enc_b2 + i * HH, bx, bx, in_mask,
                                                          HH2, HH, TT, 1.f, 0);
    }
    ln_kernel<<<(BB * TT + 255) / 256, 256>>>(bx, bn, enc_last_g, enc_last_b, in_mask, TT);
    mma_conv<3><<<dim3(TT / 128, HH / 64, BB), blk>>>(bn, enc_post_w, enc_post_b, by,
                                                      nullptr, in_mask, HH, HH, TT, 1.f, 0);

    // ---- group by segments -> [B,H,L] into bx ----
    seg_zero<<<((int)SZ_SEG + 255) / 256, 256>>>(seg, cnt);
    seg_scatter<<<dim3(TT, BB), HH>>>(by, mel2ph, seg, cnt);
    seg_div<<<(BB * HH * LL + 255) / 256, 256>>>(seg, cnt, bx);

    // ---- postnet (T = LL) ----
    for (int i = 0; i < NLB; i++) {
        ln_kernel<<<(BB * LL + 255) / 256, 256>>>(bx, bn, pn_ln_g + i * HH, pn_ln_b + i * HH,
                                                  nullptr, LL);
        mma_conv<3><<<dim3(LL / 128, HH2 / 64, BB), blk>>>(bn, pn_w1 + (size_t)i * HH2 * HH * 3,
                                                           pn_b1 + i * HH2, bm, nullptr, nullptr,
                                                           HH, HH2, LL, scale, 1);
        mma_conv<1><<<dim3(LL / 128, HH / 64, BB), blk>>>(bm, pn_w2 + (size_t)i * HH * HH2,
                                                          pn_b2 + i * HH, bx, bx, ph_mask,
                                                          HH2, HH, LL, 1.f, 0);
    }
    ln_kernel<<<(BB * LL + 255) / 256, 256>>>(bx, bn, pn_last_g, pn_last_b, ph_mask, LL);
    mma_conv<3><<<dim3(LL / 128, HH / 64, BB), blk>>>(bn, pn_post_w, pn_post_b, by,
                                                      nullptr, ph_mask, HH, HH, LL, 1.f, 0);

    // ---- proj_in -> VQ -> proj_out ----
    mma_conv<1><<<dim3(LL / 128, CVQd / 64, BB), blk>>>(by, proj_in_w, proj_in_b, bz,
                                                        nullptr, nullptr, HH, CVQd, LL, 1.f, 0);
    loss_init<<<1, 32>>>(loss);
    vq_kernel<<<dim3(LL, BB), 128>>>(bz, codebook, bq, out + (size_t)BB * HH * LL + 1, loss);
    mma_conv<1><<<dim3(LL / 128, HH / 64, BB), blk>>>(bq, proj_out_w, proj_out_b, out,
                                                      nullptr, nullptr, CVQd, HH, LL, 1.f, 0);
    loss_fin<<<1, 1>>>(loss, out + (size_t)BB * HH * LL);
}